// round 10
// baseline (speedup 1.0000x reference)
#include <cuda_runtime.h>

// Problem constants (fixed by the dataset shapes)
#define B_   32
#define NL_  13
#define L_   1024
#define D_   768
#define LCHUNKS_ 32
#define LCHUNK_  (L_ / LCHUNKS_)   // 32 rows per block

// Scratch (no allocation allowed): per-(batch,pos) weights + per-batch lengths.
__device__ float g_w[B_ * L_];
__device__ int   g_len[B_];

// ---------------------------------------------------------------------------
// Kernel 1: per-batch run-length weights + zero the output + publish lengths.
// One block per batch, L_ threads.
// Run-length algorithm: boundary flags -> block REDUCTION for num_runs
// (no scan), then per-thread LOCAL WALK to the run start/end. Adjacent vq
// pairs collide with prob ~1e-5, so runs are ~always length 1 and the walks
// are O(1) expected. Much shorter critical path than a 1024-wide scan.
// Ends with griddepcontrol.launch_dependents (PDL producer side).
//
// Integer inputs are read through an int32 view with runtime-detected element
// stride (JAX silently downcasts int64->int32 without x64). lengths are in
// [512,1024] (never 0), so word[1]==0  <=>  little-endian int64 layout.
// vq values < 320 < 2^31, so low words fully determine equality either way.
// ---------------------------------------------------------------------------
__global__ void __launch_bounds__(L_, 1)
vq_weights_kernel(const int* __restrict__ len32,
                  const int* __restrict__ vq32,
                  float* __restrict__ out)
{
    const int b    = blockIdx.x;
    const int i    = threadIdx.x;
    const int lane = i & 31;
    const int warp = i >> 5;

    __shared__ int s_bnd[L_];       // boundary flags
    __shared__ int s_v0[L_];        // staged vq low words (component 0)
    __shared__ int s_v1[L_];        // staged vq low words (component 1)
    __shared__ int s_wsum[32];      // per-warp reduction partials

    // Zero the output slice for this batch (d_out is poisoned to 0xAA).
    if (i < D_) out[b * D_ + i] = 0.0f;

    // dtype detection (uniform)
    const int stride = (len32[1] == 0) ? 2 : 1;

    const int  len   = len32[b * stride];
    const bool valid = i < len;
    if (i == 0) g_len[b] = len;

    const int ebase = (b * L_ + i) * 2;
    int v0 = vq32[(ebase + 0) * stride];
    int v1 = vq32[(ebase + 1) * stride];
    s_v0[i] = v0;
    s_v1[i] = v1;
    __syncthreads();

    // boundary = (i==0 || vq[i]!=vq[i-1]) && valid
    bool bnd;
    if (i == 0) bnd = valid;
    else        bnd = valid && (v0 != s_v0[i - 1] || v1 != s_v1[i - 1]);
    s_bnd[i] = bnd ? 1 : 0;

    // num_runs via block reduction (no scan needed)
    int r = bnd ? 1 : 0;
    #pragma unroll
    for (int off = 16; off > 0; off >>= 1)
        r += __shfl_down_sync(0xffffffffu, r, off);
    if (lane == 0) s_wsum[warp] = r;
    __syncthreads();

    int total;
    {
        int v = (lane < 32) ? s_wsum[lane] : 0;
        #pragma unroll
        for (int off = 16; off > 0; off >>= 1)
            v += __shfl_xor_sync(0xffffffffu, v, off);
        total = __shfl_sync(0xffffffffu, v, 0);   // same in all lanes of warp 0
    }
    // broadcast total via smem (all warps need it)
    if (i == 0) s_wsum[0] = total;
    __syncthreads();
    total = s_wsum[0];

    float wv = 0.0f;
    if (valid) {
        // run start: walk down to nearest boundary (expected 0 steps)
        int s = i;
        while (!s_bnd[s]) --s;
        // run end: walk up to next boundary or end of valid region
        int e = i + 1;
        while (e < len && !s_bnd[e]) ++e;
        wv = 1.0f / ((float)total * (float)(e - s));
    }
    g_w[b * L_ + i] = wv;

    // All of this block's global writes are done -> allow dependent launch.
    __syncthreads();
    asm volatile("griddepcontrol.launch_dependents;");
}

// ---------------------------------------------------------------------------
// Kernel 2: weighted pool over the LAST layer of input_feature.
// grid = (LCHUNKS_=32, B_=32) = 1024 blocks (single wave at 8 blocks/SM),
// 192 threads (one float4 column group per thread, 192*4 = 768 = D).
// R7/R9 streaming body. PDL overlap: feature data is a pure input, so blocks
// with lc < 16 (guaranteed valid: len >= 512) prefetch their first 8 rows
// BEFORE griddepcontrol.wait -- those loads stream while the producer drains.
// Only g_len/g_w reads are gated by the wait. Epilogue: one red.global.v4.f32.
// ---------------------------------------------------------------------------
__global__ void __launch_bounds__(D_ / 4, 8)
vq_pool_kernel(const float* __restrict__ feat, float* __restrict__ out)
{
    const int b  = blockIdx.y;
    const int lc = blockIdx.x;
    const int t  = threadIdx.x;     // 0..191

    const int l0 = lc * LCHUNK_;

    const float4* __restrict__ fb = (const float4*)
        (feat + ((size_t)b * NL_ + (NL_ - 1)) * (size_t)(L_ * D_));
    const float4* __restrict__ wb4 = (const float4*)(g_w + b * L_);
    float* ob = out + b * D_ + t * 4;

    float4 acc = make_float4(0.f, 0.f, 0.f, 0.f);

    if (lc < 16) {
        // Guaranteed-valid chunk (len >= 512): prefetch rows l0..l0+7 before
        // waiting on the producer. These LDGs issue and queue during the
        // weights kernel's drain -> real overlap.
        float4 f[8];
        #pragma unroll
        for (int k = 0; k < 8; ++k)
            f[k] = __ldcs(&fb[(size_t)(l0 + k) * (D_ / 4) + t]);

        asm volatile("griddepcontrol.wait;" ::: "memory");

        {
            const float4 w0 = wb4[l0 / 4 + 0];
            const float4 w1 = wb4[l0 / 4 + 1];
            const float wl[8] = { w0.x, w0.y, w0.z, w0.w, w1.x, w1.y, w1.z, w1.w };
            #pragma unroll
            for (int k = 0; k < 8; ++k) {
                acc.x = fmaf(wl[k], f[k].x, acc.x);
                acc.y = fmaf(wl[k], f[k].y, acc.y);
                acc.z = fmaf(wl[k], f[k].z, acc.z);
                acc.w = fmaf(wl[k], f[k].w, acc.w);
            }
        }

        #pragma unroll
        for (int j = 8; j < LCHUNK_; j += 8) {
            const float4 w0 = wb4[(l0 + j) / 4 + 0];
            const float4 w1 = wb4[(l0 + j) / 4 + 1];
            const float wl[8] = { w0.x, w0.y, w0.z, w0.w, w1.x, w1.y, w1.z, w1.w };
            float4 g[8];
            #pragma unroll
            for (int k = 0; k < 8; ++k)
                g[k] = __ldcs(&fb[(size_t)(l0 + j + k) * (D_ / 4) + t]);
            #pragma unroll
            for (int k = 0; k < 8; ++k) {
                acc.x = fmaf(wl[k], g[k].x, acc.x);
                acc.y = fmaf(wl[k], g[k].y, acc.y);
                acc.z = fmaf(wl[k], g[k].z, acc.z);
                acc.w = fmaf(wl[k], g[k].w, acc.w);
            }
        }
    } else {
        // Possibly-invalid chunk: must know len before touching feature rows.
        asm volatile("griddepcontrol.wait;" ::: "memory");
        if (l0 >= g_len[b]) return;     // whole chunk is zero-weight

        #pragma unroll
        for (int j = 0; j < LCHUNK_; j += 8) {
            const float4 w0 = wb4[(l0 + j) / 4 + 0];
            const float4 w1 = wb4[(l0 + j) / 4 + 1];
            const float wl[8] = { w0.x, w0.y, w0.z, w0.w, w1.x, w1.y, w1.z, w1.w };
            float4 g[8];
            #pragma unroll
            for (int k = 0; k < 8; ++k)
                g[k] = __ldcs(&fb[(size_t)(l0 + j + k) * (D_ / 4) + t]);
            #pragma unroll
            for (int k = 0; k < 8; ++k) {
                acc.x = fmaf(wl[k], g[k].x, acc.x);
                acc.y = fmaf(wl[k], g[k].y, acc.y);
                acc.z = fmaf(wl[k], g[k].z, acc.z);
                acc.w = fmaf(wl[k], g[k].w, acc.w);
            }
        }
    }

    // Single vectorized reduction (16B-aligned)
    asm volatile("red.global.add.v4.f32 [%0], {%1, %2, %3, %4};"
                 :: "l"(ob), "f"(acc.x), "f"(acc.y), "f"(acc.z), "f"(acc.w)
                 : "memory");
}

// ---------------------------------------------------------------------------
extern "C" void kernel_launch(void* const* d_in, const int* in_sizes, int n_in,
                              void* d_out, int out_size)
{
    const float* feat  = (const float*)d_in[0];   // (B, NL, L, D) f32
    const int*   len32 = (const int*)d_in[1];     // (B,) i32 or i64 (detected)
    const int*   vq32  = (const int*)d_in[2];     // (B, L, 2) i32 or i64 (detected)
    float*       out   = (float*)d_out;           // (B, D) f32

    vq_weights_kernel<<<B_, L_>>>(len32, vq32, out);

    // Pool kernel with programmatic stream serialization (PDL).
    cudaLaunchConfig_t cfg = {};
    cfg.gridDim  = dim3(LCHUNKS_, B_);
    cfg.blockDim = dim3(D_ / 4);
    cudaLaunchAttribute attr[1];
    attr[0].id = cudaLaunchAttributeProgrammaticStreamSerialization;
    attr[0].val.programmaticStreamSerializationAllowed = 1;
    cfg.attrs    = attr;
    cfg.numAttrs = 1;
    cudaLaunchKernelEx(&cfg, vq_pool_kernel, feat, out);
}